// round 4
// baseline (speedup 1.0000x reference)
#include <cuda_runtime.h>

constexpr int Bc = 512;
constexpr int Lc = 200;
constexpr int Ec = 64;

// ---------------- kernel 1 smem layout (floats) ----------------
constexpr int WSS    = 20;                       // padded ws row stride
constexpr int WS_OFF = 0;                        // ws[3][64][20]: ws[m][j][i] = Wm[h*16+i][j]
constexpr int XSS    = 68;                       // padded x stride
constexpr int XS_OFF = WS_OFF + 3 * 64 * WSS;    // xs[64][68]
constexpr int KTS    = 208;                      // padded kt stride
constexpr int KT_OFF = XS_OFF + 64 * XSS;        // kt[16][208]
constexpr int QS_OFF = KT_OFF + 16 * KTS;        // q[200][16]
constexpr int VS_OFF = QS_OFF + Lc * 16;         // v[200][16]
constexpr int WC_OFF = VS_OFF + Lc * 16;         // col sums [200]
constexpr int SP_OFF = WC_OFF + Lc;              // partials [16][16]
constexpr int SM1_F  = SP_OFF + 256;             // ~18376 floats = 73.5 KB

__device__ float g_S[Bc * Ec];
__device__ int   g_len[Bc];

extern __shared__ float sw[];

__global__ void __launch_bounds__(256, 3)
attn_head_kernel(const float* __restrict__ input,
                 const int* __restrict__ mask,
                 const float* __restrict__ pos_enc,
                 const float* __restrict__ Wk, const float* __restrict__ bk,
                 const float* __restrict__ Wv, const float* __restrict__ bv,
                 const float* __restrict__ Wq, const float* __restrict__ bq) {
    const int tid  = threadIdx.x;
    const int lane = tid & 31;
    const int wid  = tid >> 5;
    const int b    = blockIdx.x >> 2;
    const int h    = blockIdx.x & 3;

    // ---- len (prefix mask; mask is int32) ----
    int pred = (tid < Lc) && (mask[(size_t)b * Lc + tid] != 0);
    const int len = __syncthreads_count(pred);

    // ---- phase 0: weight slices (transposed) for this head ----
    for (int idx = tid; idx < 64 * 16; idx += 256) {
        int j = idx & 63, i = idx >> 6;              // j consecutive -> coalesced LDG
        int g = (h * 16 + i) * 64 + j;
        sw[WS_OFF + 0 * 64 * WSS + j * WSS + i] = Wk[g];
        sw[WS_OFF + 1 * 64 * WSS + j * WSS + i] = Wv[g];
        sw[WS_OFF + 2 * 64 * WSS + j * WSS + i] = Wq[g];
    }
    if (tid < Lc) sw[WC_OFF + tid] = 0.0f;
    __syncthreads();

    // ---- phase 1: projection (tiles of 64 rows) ----
    const int r  = tid >> 2;          // row within tile
    const int c4 = (tid & 3) * 4;     // 4 output dims
    float4 bK = *(const float4*)(bk + h * 16 + c4);
    float4 bV = *(const float4*)(bv + h * 16 + c4);
    float4 bQ = *(const float4*)(bq + h * 16 + c4);

    const int ntiles = (len + 63) >> 6;
    for (int tile = 0; tile < ntiles; tile++) {
        const int tb = tile * 64;
        // stage x = input + pos_enc
        const float4* in4 = (const float4*)(input + ((size_t)b * Lc + tb) * Ec);
        const float4* pe4 = (const float4*)(pos_enc + (size_t)tb * Ec);
#pragma unroll
        for (int v = 0; v < 4; v++) {
            int f = tid + v * 256;                // 0..1023
            int rr = f >> 4, cc = (f & 15) * 4;
            float4 val = make_float4(0.f, 0.f, 0.f, 0.f);
            if (tb + rr < Lc) {
                float4 a = in4[f], p = pe4[f];
                val = make_float4(a.x + p.x, a.y + p.y, a.z + p.z, a.w + p.w);
            }
            *(float4*)(sw + XS_OFF + rr * XSS + cc) = val;
        }
        __syncthreads();

        float acc[3][4];
#pragma unroll
        for (int m = 0; m < 3; m++)
#pragma unroll
            for (int i = 0; i < 4; i++) acc[m][i] = 0.f;

#pragma unroll 8
        for (int j = 0; j < 64; j++) {
            float x = sw[XS_OFF + r * XSS + j];
#pragma unroll
            for (int m = 0; m < 3; m++) {
                float4 w = *(const float4*)(sw + WS_OFF + m * 64 * WSS + j * WSS + c4);
                acc[m][0] = fmaf(x, w.x, acc[m][0]);
                acc[m][1] = fmaf(x, w.y, acc[m][1]);
                acc[m][2] = fmaf(x, w.z, acc[m][2]);
                acc[m][3] = fmaf(x, w.w, acc[m][3]);
            }
        }

        const int t = tb + r;
        if (t < len) {
            sw[KT_OFF + (c4 + 0) * KTS + t] = acc[0][0] + bK.x;
            sw[KT_OFF + (c4 + 1) * KTS + t] = acc[0][1] + bK.y;
            sw[KT_OFF + (c4 + 2) * KTS + t] = acc[0][2] + bK.z;
            sw[KT_OFF + (c4 + 3) * KTS + t] = acc[0][3] + bK.w;
            *(float4*)(sw + VS_OFF + t * 16 + c4) =
                make_float4(acc[1][0] + bV.x, acc[1][1] + bV.y,
                            acc[1][2] + bV.z, acc[1][3] + bV.w);
            *(float4*)(sw + QS_OFF + t * 16 + c4) =
                make_float4((acc[2][0] + bQ.x) * 0.25f, (acc[2][1] + bQ.y) * 0.25f,
                            (acc[2][2] + bQ.z) * 0.25f, (acc[2][3] + bQ.w) * 0.25f);
        }
        __syncthreads();
    }

    // ---- phase 2: scores + softmax (no max-subtract; bounded scores), column sums ----
    // 2 query rows per warp iteration (register pressure: fits 3 CTAs/SM)
    float wacc[7];
#pragma unroll
    for (int m = 0; m < 7; m++) wacc[m] = 0.f;

    for (int qb = wid * 2; qb < len; qb += 16) {
        float qv[2][16];
#pragma unroll
        for (int qq = 0; qq < 2; qq++) {
            int q = qb + qq; q = (q < len) ? q : 0;
            const float4* p = (const float4*)(sw + QS_OFF + q * 16);
#pragma unroll
            for (int jj = 0; jj < 4; jj++) {
                float4 v = p[jj];
                qv[qq][4 * jj + 0] = v.x; qv[qq][4 * jj + 1] = v.y;
                qv[qq][4 * jj + 2] = v.z; qv[qq][4 * jj + 3] = v.w;
            }
        }

        float ee[7][2];
#pragma unroll
        for (int m = 0; m < 7; m++) {
            int k = m * 32 + lane;
            if (m * 32 < len && k < len) {
                const float* kp = sw + KT_OFF + k;
                float a0 = 0.f, a1 = 0.f;
#pragma unroll
                for (int j = 0; j < 16; j++) {
                    float kw = kp[j * KTS];
                    a0 = fmaf(kw, qv[0][j], a0);
                    a1 = fmaf(kw, qv[1][j], a1);
                }
                ee[m][0] = __expf(a0); ee[m][1] = __expf(a1);
            } else {
                ee[m][0] = 0.f; ee[m][1] = 0.f;
            }
        }

        // per-q row sums (tree), then 2 interleaved warp reductions
        float z0, z1;
        {
            float a01 = ee[0][0] + ee[1][0];
            float a23 = ee[2][0] + ee[3][0];
            float a45 = ee[4][0] + ee[5][0];
            z0 = (a01 + a23) + (a45 + ee[6][0]);
            float b01 = ee[0][1] + ee[1][1];
            float b23 = ee[2][1] + ee[3][1];
            float b45 = ee[4][1] + ee[5][1];
            z1 = (b01 + b23) + (b45 + ee[6][1]);
        }
#pragma unroll
        for (int o = 16; o; o >>= 1) {
            z0 += __shfl_xor_sync(0xffffffffu, z0, o);
            z1 += __shfl_xor_sync(0xffffffffu, z1, o);
        }
        float inv0 = (qb + 0 < len) ? __fdividef(1.0f, z0) : 0.0f;
        float inv1 = (qb + 1 < len) ? __fdividef(1.0f, z1) : 0.0f;
#pragma unroll
        for (int m = 0; m < 7; m++) {
            float t0 = fmaf(ee[m][0], inv0, wacc[m]);
            wacc[m]  = fmaf(ee[m][1], inv1, t0);
        }
    }

#pragma unroll
    for (int m = 0; m < 7; m++) {
        int k = m * 32 + lane;
        if (k < Lc) atomicAdd(&sw[WC_OFF + k], wacc[m]);
    }
    __syncthreads();

    // ---- phase 3: S[c] = sum_k wc[k] * V[k][c] ----
    {
        const int c = tid & 15, part = tid >> 4;
        float acc = 0.f;
        for (int k = part; k < len; k += 16)
            acc = fmaf(sw[WC_OFF + k], sw[VS_OFF + k * 16 + c], acc);
        sw[SP_OFF + part * 16 + c] = acc;
    }
    __syncthreads();
    if (tid < 16) {
        float s = 0.f;
#pragma unroll
        for (int p = 0; p < 16; p++) s += sw[SP_OFF + p * 16 + tid];
        g_S[b * 64 + h * 16 + tid] = s;
    }
    if (tid == 0 && h == 0) g_len[b] = len;
}

// ---------------- kernel 2: out = (S @ WfT + bf*len) / (len+1e-8) ----------------
// 2 batches per block, 128 threads; grid 256 for better SM coverage
__global__ void __launch_bounds__(128)
pool_proj_kernel(const float* __restrict__ Wf, const float* __restrict__ bf,
                 float* __restrict__ out) {
    __shared__ float wf[64 * 65];
    __shared__ float ss[2 * 64];
    const int tid = threadIdx.x;
    const int b0 = blockIdx.x * 2;

    for (int idx = tid; idx < 4096; idx += 128) {
        int e = idx >> 6, c = idx & 63;
        wf[e * 65 + c] = Wf[idx];
    }
    ss[tid] = g_S[b0 * 64 + tid];
    __syncthreads();

    const int bb = tid >> 6, e = tid & 63;
    float acc = 0.f;
#pragma unroll 16
    for (int c = 0; c < 64; c++)
        acc = fmaf(ss[bb * 64 + c], wf[e * 65 + c], acc);
    const float lenf = (float)g_len[b0 + bb];
    const float invd = 1.0f / (lenf + 1e-8f);
    out[(b0 + bb) * 64 + e] = acc * invd + bf[e] * lenf * invd;
}

extern "C" void kernel_launch(void* const* d_in, const int* in_sizes, int n_in,
                              void* d_out, int out_size) {
    const float* input   = (const float*)d_in[0];
    const int*   mask    = (const int*)d_in[1];
    const float* pos_enc = (const float*)d_in[2];
    const float* Wk      = (const float*)d_in[3];
    const float* bk      = (const float*)d_in[4];
    const float* Wv      = (const float*)d_in[5];
    const float* bv      = (const float*)d_in[6];
    const float* Wq      = (const float*)d_in[7];
    const float* bq      = (const float*)d_in[8];
    const float* Wf      = (const float*)d_in[9];
    const float* bf      = (const float*)d_in[10];
    float* out           = (float*)d_out;

    const size_t smem1 = (size_t)SM1_F * sizeof(float);
    cudaFuncSetAttribute(attn_head_kernel,
                         cudaFuncAttributeMaxDynamicSharedMemorySize, (int)smem1);
    attn_head_kernel<<<Bc * 4, 256, smem1>>>(input, mask, pos_enc,
                                             Wk, bk, Wv, bv, Wq, bq);
    pool_proj_kernel<<<Bc / 2, 128>>>(Wf, bf, out);
}

// round 5
// speedup vs baseline: 1.3365x; 1.3365x over previous
#include <cuda_runtime.h>

constexpr int Bc = 512;
constexpr int Lc = 200;
constexpr int Ec = 64;

// ---------------- smem layout (floats) ----------------
constexpr int WSS    = 20;                       // ws[3][64][20]: ws[m][j][i] = Wm[h*16+i][j]
constexpr int WS_OFF = 0;
constexpr int XSS    = 68;                       // xs[128][68]
constexpr int XS_OFF = WS_OFF + 3 * 64 * WSS;
constexpr int KTS    = 208;                      // kt[16][208]: kt[j][t]  (t contiguous!)
constexpr int KT_OFF = XS_OFF + 128 * XSS;
constexpr int QS_OFF = KT_OFF + 16 * KTS;        // q[200][16] (pre-scaled by 0.25*log2e)
constexpr int VS_OFF = QS_OFF + Lc * 16;         // v[200][16]
constexpr int WC_OFF = VS_OFF + Lc * 16;         // col sums [200]
constexpr int SP_OFF = WC_OFF + Lc + 8;          // partials [16][16]
constexpr int SM1_F  = SP_OFF + 256;             // ~22744 floats ≈ 89 KB

__device__ __forceinline__ float ex2f(float x) {
    float y;
    asm("ex2.approx.ftz.f32 %0, %1;" : "=f"(y) : "f"(x));
    return y;
}

extern __shared__ float sw[];

__global__ void __launch_bounds__(256, 2)
attn_head_kernel(const float* __restrict__ input,
                 const int* __restrict__ mask,
                 const float* __restrict__ pos_enc,
                 const float* __restrict__ Wk, const float* __restrict__ bk,
                 const float* __restrict__ Wv, const float* __restrict__ bv,
                 const float* __restrict__ Wq, const float* __restrict__ bq,
                 const float* __restrict__ Wf, const float* __restrict__ bf,
                 float* __restrict__ out) {
    const int tid  = threadIdx.x;
    const int lane = tid & 31;
    const int wid  = tid >> 5;
    const int b    = blockIdx.x >> 2;
    const int h    = blockIdx.x & 3;

    // ---- len (prefix mask; mask is int32) ----
    int pred = (tid < Lc) && (mask[(size_t)b * Lc + tid] != 0);
    const int len = __syncthreads_count(pred);

    // ---- phase 0: head weight slices (transposed) ----
    for (int idx = tid; idx < 64 * 16; idx += 256) {
        int j = idx & 63, i = idx >> 6;
        int g = (h * 16 + i) * 64 + j;
        sw[WS_OFF + 0 * 64 * WSS + j * WSS + i] = Wk[g];
        sw[WS_OFF + 1 * 64 * WSS + j * WSS + i] = Wv[g];
        sw[WS_OFF + 2 * 64 * WSS + j * WSS + i] = Wq[g];
    }
    if (tid < Lc) sw[WC_OFF + tid] = 0.0f;
    __syncthreads();

    // ---- phase 1: projections, 128-row tiles, 2 rows per thread ----
    const int r  = tid >> 2;          // 0..63
    const int c4 = (tid & 3) * 4;     // 4 output dims of this head
    const float QSC = 0.36067376022224085f;   // 0.25 * log2(e)
    float4 bK = *(const float4*)(bk + h * 16 + c4);
    float4 bV = *(const float4*)(bv + h * 16 + c4);
    float4 bQ = *(const float4*)(bq + h * 16 + c4);

    const int ntiles = (len + 127) >> 7;
    for (int tile = 0; tile < ntiles; tile++) {
        const int tb = tile * 128;
        const float4* in4 = (const float4*)(input + ((size_t)b * Lc + tb) * Ec);
        const float4* pe4 = (const float4*)(pos_enc + (size_t)tb * Ec);
#pragma unroll
        for (int v = 0; v < 8; v++) {
            int f = tid + v * 256;               // 0..2047
            int rr = f >> 4, cc = (f & 15) * 4;
            float4 val = make_float4(0.f, 0.f, 0.f, 0.f);
            if (tb + rr < Lc) {
                float4 a = in4[f], p = pe4[f];
                val = make_float4(a.x + p.x, a.y + p.y, a.z + p.z, a.w + p.w);
            }
            *(float4*)(sw + XS_OFF + rr * XSS + cc) = val;
        }
        __syncthreads();

        const int t0 = tb + r, t1 = tb + 64 + r;
        if (t0 < len) {
            float acc[2][3][4];
#pragma unroll
            for (int rr = 0; rr < 2; rr++)
#pragma unroll
                for (int m = 0; m < 3; m++)
#pragma unroll
                    for (int i = 0; i < 4; i++) acc[rr][m][i] = 0.f;

#pragma unroll 8
            for (int j = 0; j < 64; j++) {
                float x0 = sw[XS_OFF + r * XSS + j];
                float x1 = sw[XS_OFF + (64 + r) * XSS + j];
#pragma unroll
                for (int m = 0; m < 3; m++) {
                    float4 w = *(const float4*)(sw + WS_OFF + m * 64 * WSS + j * WSS + c4);
                    acc[0][m][0] = fmaf(x0, w.x, acc[0][m][0]);
                    acc[0][m][1] = fmaf(x0, w.y, acc[0][m][1]);
                    acc[0][m][2] = fmaf(x0, w.z, acc[0][m][2]);
                    acc[0][m][3] = fmaf(x0, w.w, acc[0][m][3]);
                    acc[1][m][0] = fmaf(x1, w.x, acc[1][m][0]);
                    acc[1][m][1] = fmaf(x1, w.y, acc[1][m][1]);
                    acc[1][m][2] = fmaf(x1, w.z, acc[1][m][2]);
                    acc[1][m][3] = fmaf(x1, w.w, acc[1][m][3]);
                }
            }
#pragma unroll
            for (int rr = 0; rr < 2; rr++) {
                int t = (rr == 0) ? t0 : t1;
                if (t < len) {
                    sw[KT_OFF + (c4 + 0) * 0 + 0] = sw[KT_OFF];  // no-op placeholder removed below
                }
            }
            // K: kt[j][t] layout (j = dim, t contiguous)
            if (t0 < len) {
                sw[KT_OFF + (c4 + 0) * KTS + t0] = acc[0][0][0] + bK.x;
                sw[KT_OFF + (c4 + 1) * KTS + t0] = acc[0][0][1] + bK.y;
                sw[KT_OFF + (c4 + 2) * KTS + t0] = acc[0][0][2] + bK.z;
                sw[KT_OFF + (c4 + 3) * KTS + t0] = acc[0][0][3] + bK.w;
                *(float4*)(sw + VS_OFF + t0 * 16 + c4) =
                    make_float4(acc[0][1][0] + bV.x, acc[0][1][1] + bV.y,
                                acc[0][1][2] + bV.z, acc[0][1][3] + bV.w);
                *(float4*)(sw + QS_OFF + t0 * 16 + c4) =
                    make_float4((acc[0][2][0] + bQ.x) * QSC, (acc[0][2][1] + bQ.y) * QSC,
                                (acc[0][2][2] + bQ.z) * QSC, (acc[0][2][3] + bQ.w) * QSC);
            }
            if (t1 < len) {
                sw[KT_OFF + (c4 + 0) * KTS + t1] = acc[1][0][0] + bK.x;
                sw[KT_OFF + (c4 + 1) * KTS + t1] = acc[1][0][1] + bK.y;
                sw[KT_OFF + (c4 + 2) * KTS + t1] = acc[1][0][2] + bK.z;
                sw[KT_OFF + (c4 + 3) * KTS + t1] = acc[1][0][3] + bK.w;
                *(float4*)(sw + VS_OFF + t1 * 16 + c4) =
                    make_float4(acc[1][1][0] + bV.x, acc[1][1][1] + bV.y,
                                acc[1][1][2] + bV.z, acc[1][1][3] + bV.w);
                *(float4*)(sw + QS_OFF + t1 * 16 + c4) =
                    make_float4((acc[1][2][0] + bQ.x) * QSC, (acc[1][2][1] + bQ.y) * QSC,
                                (acc[1][2][2] + bQ.z) * QSC, (acc[1][2][3] + bQ.w) * QSC);
            }
        }
        __syncthreads();
    }

    // ---- phase 2: scores (log2 domain) + softmax + column sums ----
    // lane owns keys k = kb*64 + lane*2 + {0,1};  4 query rows per warp iteration
    const int nb = (len + 63) >> 6;              // 1..4 k-blocks of 64
    float wacc[4][2];
#pragma unroll
    for (int kb = 0; kb < 4; kb++) { wacc[kb][0] = 0.f; wacc[kb][1] = 0.f; }

    for (int qb = wid * 4; qb < len; qb += 32) {
        float qv[4][16];
#pragma unroll
        for (int qq = 0; qq < 4; qq++) {
            int q = qb + qq; q = (q < len) ? q : 0;
            const float4* p = (const float4*)(sw + QS_OFF + q * 16);
#pragma unroll
            for (int jj = 0; jj < 4; jj++) {
                float4 v = p[jj];
                qv[qq][4 * jj + 0] = v.x; qv[qq][4 * jj + 1] = v.y;
                qv[qq][4 * jj + 2] = v.z; qv[qq][4 * jj + 3] = v.w;
            }
        }

        float ee[4][4][2];                        // [kb][q][i]
        float z[4] = {0.f, 0.f, 0.f, 0.f};
#pragma unroll
        for (int kb = 0; kb < 4; kb++) {
            if (kb < nb) {
                const int k0 = kb * 64 + lane * 2;
                const float* kp = sw + KT_OFF + k0;
                float a[4][2];
#pragma unroll
                for (int qq = 0; qq < 4; qq++) { a[qq][0] = 0.f; a[qq][1] = 0.f; }
#pragma unroll
                for (int j = 0; j < 16; j++) {
                    float2 kt2 = *(const float2*)(kp + j * KTS);
#pragma unroll
                    for (int qq = 0; qq < 4; qq++) {
                        a[qq][0] = fmaf(kt2.x, qv[qq][j], a[qq][0]);
                        a[qq][1] = fmaf(kt2.y, qv[qq][j], a[qq][1]);
                    }
                }
                const bool ok0 = (k0 + 0) < len;
                const bool ok1 = (k0 + 1) < len;
#pragma unroll
                for (int qq = 0; qq < 4; qq++) {
                    float e0 = ok0 ? ex2f(a[qq][0]) : 0.f;
                    float e1 = ok1 ? ex2f(a[qq][1]) : 0.f;
                    ee[kb][qq][0] = e0; ee[kb][qq][1] = e1;
                    z[qq] += e0 + e1;
                }
            } else {
#pragma unroll
                for (int qq = 0; qq < 4; qq++) { ee[kb][qq][0] = 0.f; ee[kb][qq][1] = 0.f; }
            }
        }

#pragma unroll
        for (int o = 16; o; o >>= 1) {
            z[0] += __shfl_xor_sync(0xffffffffu, z[0], o);
            z[1] += __shfl_xor_sync(0xffffffffu, z[1], o);
            z[2] += __shfl_xor_sync(0xffffffffu, z[2], o);
            z[3] += __shfl_xor_sync(0xffffffffu, z[3], o);
        }
        float inv[4];
#pragma unroll
        for (int qq = 0; qq < 4; qq++)
            inv[qq] = (qb + qq < len) ? __fdividef(1.0f, z[qq]) : 0.0f;
#pragma unroll
        for (int kb = 0; kb < 4; kb++) {
            if (kb < nb) {
#pragma unroll
                for (int qq = 0; qq < 4; qq++) {
                    wacc[kb][0] = fmaf(ee[kb][qq][0], inv[qq], wacc[kb][0]);
                    wacc[kb][1] = fmaf(ee[kb][qq][1], inv[qq], wacc[kb][1]);
                }
            }
        }
    }

#pragma unroll
    for (int kb = 0; kb < 4; kb++) {
        if (kb < nb) {
            int k = kb * 64 + lane * 2;
            if (k < Lc)     atomicAdd(&sw[WC_OFF + k],     wacc[kb][0]);
            if (k + 1 < Lc) atomicAdd(&sw[WC_OFF + k + 1], wacc[kb][1]);
        }
    }
    __syncthreads();

    // ---- phase 3: S[c] = sum_k wc[k] * V[k][c] ----
    {
        const int c = tid & 15, part = tid >> 4;
        float acc = 0.f;
        for (int k = part; k < len; k += 16)
            acc = fmaf(sw[WC_OFF + k], sw[VS_OFF + k * 16 + c], acc);
        sw[SP_OFF + part * 16 + c] = acc;
    }
    __syncthreads();
    if (tid < 16) {
        float s = 0.f;
#pragma unroll
        for (int p = 0; p < 16; p++) s += sw[SP_OFF + p * 16 + tid];
        sw[SP_OFF + tid] = s;   // own slot: safe (only p=0 term read by self)
    }
    __syncthreads();

    // ---- phase 4 (fused): out[b][e] += inv*(S_head . Wf[e, h*16:]) (+ bf term on h==0) ----
    if (tid < 64) {
        float acc = 0.f;
        const float* wfr = Wf + tid * 64 + h * 16;
#pragma unroll
        for (int i = 0; i < 16; i++)
            acc = fmaf(sw[SP_OFF + i], wfr[i], acc);
        const float lenf = (float)len;
        const float invd = 1.0f / (lenf + 1e-8f);
        float val = acc * invd;
        if (h == 0) val = fmaf(bf[tid], lenf * invd, val);
        atomicAdd(out + b * 64 + tid, val);
    }
}

extern "C" void kernel_launch(void* const* d_in, const int* in_sizes, int n_in,
                              void* d_out, int out_size) {
    const float* input   = (const float*)d_in[0];
    const int*   mask    = (const int*)d_in[1];
    const float* pos_enc = (const float*)d_in[2];
    const float* Wk      = (const float*)d_in[3];
    const float* bk      = (const float*)d_in[4];
    const float* Wv      = (const float*)d_in[5];
    const float* bv      = (const float*)d_in[6];
    const float* Wq      = (const float*)d_in[7];
    const float* bq      = (const float*)d_in[8];
    const float* Wf      = (const float*)d_in[9];
    const float* bf      = (const float*)d_in[10];
    float* out           = (float*)d_out;

    cudaMemsetAsync(out, 0, (size_t)Bc * Ec * sizeof(float), 0);

    const size_t smem1 = (size_t)SM1_F * sizeof(float);
    cudaFuncSetAttribute(attn_head_kernel,
                         cudaFuncAttributeMaxDynamicSharedMemorySize, (int)smem1);
    attn_head_kernel<<<Bc * 4, 256, smem1>>>(input, mask, pos_enc,
                                             Wk, bk, Wv, bv, Wq, bq, Wf, bf, out);
}